// round 15
// baseline (speedup 1.0000x reference)
#include <cuda_runtime.h>

#define HH 112
#define WW 112
#define CCH 64
#define BBATCH 32
#define ZSPLIT 4          // CTAs per image (row quarters)
#define BANDS 2           // bands per CTA
#define TBANDS 8          // total bands per image
#define BH 14             // output rows per band
#define NSTEP 18          // BH + 4 halo rows
#define BX 32             // lanes; 0..27 own 4-col groups
#define NCG 28
#define NTHREADS 64

__device__ __forceinline__ float frcp(float d) {
    float r; asm("rcp.approx.f32 %0, %1;" : "=f"(r) : "f"(d)); return r;
}
__device__ __forceinline__ int iclamp(int v, int lo, int hi) {
    return v < lo ? lo : (v > hi ? hi : v);
}

__global__ __launch_bounds__(NTHREADS, 16)
void bionorm_kernel(const float* __restrict__ x,
                    const float* __restrict__ sigma,
                    const float* __restrict__ pow_p,
                    const float* __restrict__ sum_kernel,
                    const float* __restrict__ weight,
                    const float* __restrict__ bias,
                    float* __restrict__ out)
{
    __shared__ float kc_sh[25];
    __shared__ float sp_sh;
    __shared__ int   uni_sh;

    const int tx  = threadIdx.x;             // lane: column group (0..27 active)
    const int ty  = threadIdx.y;             // band-in-CTA 0..1
    const int tid = ty * BX + tx;
    const int c   = blockIdx.x;
    const int b   = blockIdx.y;
    const int gband = blockIdx.z * BANDS + ty;   // global band 0..7
    const int r0  = gband * BH;
    const int w4  = 4 * tx;
    const bool act = (tx < NCG);
    const int wl4 = act ? w4 : WW - 4;       // safe col for idle lanes

    const float p  = pow_p[c];
    const bool  sq = (p == 2.0f);

    if (tid < 25) kc_sh[tid] = sum_kernel[c * 25 + tid];
    if (tid == 0) {
        float s = sigma[c];
        sp_sh = sq ? s * s : powf(s, p);
        const float* kp = sum_kernel + c * 25;
        float k0 = kp[0];
        int u = 1;
        #pragma unroll
        for (int i = 1; i < 25; i++) u &= (kp[i] == k0);
        uni_sh = u;
    }
    __syncthreads();

    const float* __restrict__ xin  = x   + (size_t)(b * CCH + c) * (HH * WW);
    float* __restrict__       oimg = out + (size_t)(b * CCH + c) * (HH * WW);
    const float sp  = sp_sh;
    const float wgt = weight[c];
    const float bs  = bias[c];

    if (uni_sh) {
        // ===== FAST PATH: vertical-first register-streaming box filter =====
        // out = xp * rcp(fma(S, k0/wgt, sp/wgt)) + bs   (wgt folded into denom)
        const float iw  = frcp(wgt);
        const float k0w = kc_sh[0] * iw;
        const float spw = sp * iw;

        float4 hist[5];                      // raw xp history (circular 5)
        float4 vs4 = make_float4(0.f, 0.f, 0.f, 0.f);   // running vertical 5-sum of xp
        float4 vsf = make_float4(0.f, 0.f, 0.f, 0.f);   // vs at center 109 (last band)
        #pragma unroll
        for (int q = 0; q < 5; q++) hist[q] = make_float4(0.f, 0.f, 0.f, 0.f);

        #pragma unroll
        for (int i = 0; i < NSTEP; i++) {
            const int lr = iclamp(r0 - 2 + i, 0, HH - 1);
            float4 v = *(const float4*)&xin[lr * WW + wl4];
            float4 xp;
            if (sq) { xp.x = v.x*v.x; xp.y = v.y*v.y; xp.z = v.z*v.z; xp.w = v.w*v.w; }
            else    { xp.x = powf(v.x,p); xp.y = powf(v.y,p); xp.z = powf(v.z,p); xp.w = powf(v.w,p); }

            // sliding vertical 5-sum of raw xp (no SHFL on the carried chain)
            float4& old = hist[i % 5];
            vs4.x += xp.x - old.x;  vs4.y += xp.y - old.y;
            vs4.z += xp.z - old.z;  vs4.w += xp.w - old.w;
            old = xp;

            if (i == NSTEP - 3) { if (gband == TBANDS - 1) vsf = vs4; }  // center 109

            if (i >= 4) {
                // select vertical sums (row-replication for rows 110/111)
                float4 vsel = vs4;
                if (i >= NSTEP - 2) { if (gband == TBANDS - 1) vsel = vsf; }

                // horizontal 5-tap on vertical sums (emit-time only)
                float Lz = __shfl_up_sync(0xffffffffu,   vsel.z, 1);
                float Lw = __shfl_up_sync(0xffffffffu,   vsel.w, 1);
                float Rx = __shfl_down_sync(0xffffffffu, vsel.x, 1);
                float Ry = __shfl_down_sync(0xffffffffu, vsel.y, 1);
                float m = vsel.x + vsel.y + vsel.z;
                float t = vsel.w + Rx;
                float4 sfv;
                sfv.x = Lz + Lw + m;
                sfv.y = Lw + m + vsel.w;
                sfv.z = m + t;
                sfv.w = vsel.y + vsel.z + t + Ry;
                // horizontal conv-output replication (cols 0,1 <- 2; 110,111 <- 109)
                if (tx == 0)       { sfv.x = sfv.z; sfv.y = sfv.z; }
                if (tx == NCG - 1) { sfv.z = sfv.y; sfv.w = sfv.y; }

                // numerator: raw xp of emitted row, straight from history
                const float4 xpv = hist[(i - 2) % 5];
                if (act && (i >= 6 || gband != 0)) {
                    const int hrow = r0 + i - 4;
                    float4 o;
                    o.x = fmaf(xpv.x, frcp(fmaf(sfv.x, k0w, spw)), bs);
                    o.y = fmaf(xpv.y, frcp(fmaf(sfv.y, k0w, spw)), bs);
                    o.z = fmaf(xpv.z, frcp(fmaf(sfv.z, k0w, spw)), bs);
                    o.w = fmaf(xpv.w, frcp(fmaf(sfv.w, k0w, spw)), bs);
                    *(float4*)&oimg[hrow * WW + w4] = o;
                }
                // rows 0,1 replicate sf(center 2) at i==6; reload x (L1 hit)
                if (i == 6) {
                    if (gband == 0 && act) {
                        #pragma unroll
                        for (int rr = 0; rr < 2; rr++) {
                            float4 vv = *(const float4*)&xin[rr * WW + w4];
                            float4 xq;
                            if (sq) { xq.x=vv.x*vv.x; xq.y=vv.y*vv.y; xq.z=vv.z*vv.z; xq.w=vv.w*vv.w; }
                            else    { xq.x=powf(vv.x,p); xq.y=powf(vv.y,p); xq.z=powf(vv.z,p); xq.w=powf(vv.w,p); }
                            float4 o;
                            o.x = fmaf(xq.x, frcp(fmaf(sfv.x, k0w, spw)), bs);
                            o.y = fmaf(xq.y, frcp(fmaf(sfv.y, k0w, spw)), bs);
                            o.z = fmaf(xq.z, frcp(fmaf(sfv.z, k0w, spw)), bs);
                            o.w = fmaf(xq.w, frcp(fmaf(sfv.w, k0w, spw)), bs);
                            *(float4*)&oimg[rr * WW + w4] = o;
                        }
                    }
                }
            }
        }
    } else {
        // ========== GENERAL PATH: direct 25-tap from global (fallback) =====
        if (act) {
            float kc[25];
            #pragma unroll
            for (int q = 0; q < 25; q++) kc[q] = kc_sh[q];
            for (int j = 0; j < BH; j++) {
                const int hrow = r0 + j;
                const int hc = iclamp(hrow, 2, HH - 3);
                float4 o;
                float* op = &o.x;
                #pragma unroll
                for (int jj = 0; jj < 4; jj++) {
                    const int w  = w4 + jj;
                    const int wc = iclamp(w, 2, WW - 3);
                    float acc = 0.0f;
                    #pragma unroll
                    for (int ki = 0; ki < 5; ki++) {
                        const float* row = &xin[(hc + ki - 2) * WW + (wc - 2)];
                        #pragma unroll
                        for (int kj = 0; kj < 5; kj++) {
                            float xv = row[kj];
                            float xpv = sq ? xv * xv : powf(xv, p);
                            acc = fmaf(kc[ki * 5 + kj], xpv, acc);
                        }
                    }
                    float xv = xin[hrow * WW + w];
                    float xpv = sq ? xv * xv : powf(xv, p);
                    op[jj] = wgt * xpv / (sp + acc) + bs;
                }
                *(float4*)&oimg[hrow * WW + w4] = o;
            }
        }
    }
}

extern "C" void kernel_launch(void* const* d_in, const int* in_sizes, int n_in,
                              void* d_out, int out_size)
{
    const float* x          = (const float*)d_in[0];
    const float* sigma      = (const float*)d_in[1];
    const float* pow_p      = (const float*)d_in[2];
    const float* sum_kernel = (const float*)d_in[3];
    const float* weight     = (const float*)d_in[4];
    const float* bias       = (const float*)d_in[5];
    float* out = (float*)d_out;

    dim3 grid(CCH, BBATCH, ZSPLIT);   // 8192 CTAs
    dim3 block(BX, BANDS, 1);         // 64 threads
    bionorm_kernel<<<grid, block>>>(x, sigma, pow_p, sum_kernel, weight, bias, out);
}

// round 16
// speedup vs baseline: 1.2683x; 1.2683x over previous
#include <cuda_runtime.h>

#define HH 112
#define WW 112
#define CCH 64
#define BBATCH 32
#define ZSPLIT 2          // CTAs per image (row halves)
#define BANDS 4           // bands per CTA
#define TBANDS 8          // total bands per image
#define BH 14             // output rows per band
#define NSTEP 18          // BH + 4 halo rows
#define BX 32             // lanes; 0..27 own 4-col groups
#define NCG 28
#define NTHREADS 128

__device__ __forceinline__ float frcp(float d) {
    float r; asm("rcp.approx.f32 %0, %1;" : "=f"(r) : "f"(d)); return r;
}
__device__ __forceinline__ int iclamp(int v, int lo, int hi) {
    return v < lo ? lo : (v > hi ? hi : v);
}

__global__ __launch_bounds__(NTHREADS, 7)
void bionorm_kernel(const float* __restrict__ x,
                    const float* __restrict__ sigma,
                    const float* __restrict__ pow_p,
                    const float* __restrict__ sum_kernel,
                    const float* __restrict__ weight,
                    const float* __restrict__ bias,
                    float* __restrict__ out)
{
    __shared__ float kc_sh[25];
    __shared__ float sp_sh;
    __shared__ int   uni_sh;

    const int tx  = threadIdx.x;             // lane: column group (0..27 active)
    const int ty  = threadIdx.y;             // band-in-CTA 0..3
    const int tid = ty * BX + tx;
    const int c   = blockIdx.x;
    const int b   = blockIdx.y;
    const int gband = blockIdx.z * BANDS + ty;   // global band 0..7
    const int r0  = gband * BH;
    const int w4  = 4 * tx;
    const bool act = (tx < NCG);
    const int wl4 = act ? w4 : WW - 4;       // safe col for idle lanes

    const float p  = pow_p[c];
    const bool  sq = (p == 2.0f);

    if (tid < 25) kc_sh[tid] = sum_kernel[c * 25 + tid];
    if (tid == 0) {
        float s = sigma[c];
        sp_sh = sq ? s * s : powf(s, p);
        const float* kp = sum_kernel + c * 25;
        float k0 = kp[0];
        int u = 1;
        #pragma unroll
        for (int i = 1; i < 25; i++) u &= (kp[i] == k0);
        uni_sh = u;
    }
    __syncthreads();

    const float* __restrict__ xin  = x   + (size_t)(b * CCH + c) * (HH * WW);
    float* __restrict__       oimg = out + (size_t)(b * CCH + c) * (HH * WW);
    const float sp  = sp_sh;
    const float wgt = weight[c];
    const float bs  = bias[c];

    if (uni_sh) {
        // ===== FAST PATH: vertical-first streaming, 1-deep load pipeline ====
        // out = xp * rcp(fma(S, k0/wgt, sp/wgt)) + bs   (wgt folded into denom)
        const float iw  = frcp(wgt);
        const float k0w = kc_sh[0] * iw;
        const float spw = sp * iw;

        float4 hist[5];                      // raw xp history (circular 5)
        float4 vs4 = make_float4(0.f, 0.f, 0.f, 0.f);   // running vertical 5-sum
        float4 vsf = make_float4(0.f, 0.f, 0.f, 0.f);   // vs at center 109 (last band)
        #pragma unroll
        for (int q = 0; q < 5; q++) hist[q] = make_float4(0.f, 0.f, 0.f, 0.f);

        // prologue: preload step 0
        float4 vnext = *(const float4*)&xin[iclamp(r0 - 2, 0, HH - 1) * WW + wl4];

        #pragma unroll
        for (int i = 0; i < NSTEP; i++) {
            float4 v = vnext;
            if (i + 1 < NSTEP) {             // issue next load before consuming v
                const int lr1 = iclamp(r0 - 1 + i, 0, HH - 1);
                vnext = *(const float4*)&xin[lr1 * WW + wl4];
            }
            float4 xp;
            if (sq) { xp.x = v.x*v.x; xp.y = v.y*v.y; xp.z = v.z*v.z; xp.w = v.w*v.w; }
            else    { xp.x = powf(v.x,p); xp.y = powf(v.y,p); xp.z = powf(v.z,p); xp.w = powf(v.w,p); }

            // sliding vertical 5-sum of raw xp
            float4& old = hist[i % 5];
            vs4.x += xp.x - old.x;  vs4.y += xp.y - old.y;
            vs4.z += xp.z - old.z;  vs4.w += xp.w - old.w;
            old = xp;

            if (i == NSTEP - 3) { if (gband == TBANDS - 1) vsf = vs4; }  // center 109

            if (i >= 4) {
                // select vertical sums (row-replication for rows 110/111)
                float4 vsel = vs4;
                if (i >= NSTEP - 2) { if (gband == TBANDS - 1) vsel = vsf; }

                // horizontal 5-tap on vertical sums (emit-time only)
                float Lz = __shfl_up_sync(0xffffffffu,   vsel.z, 1);
                float Lw = __shfl_up_sync(0xffffffffu,   vsel.w, 1);
                float Rx = __shfl_down_sync(0xffffffffu, vsel.x, 1);
                float Ry = __shfl_down_sync(0xffffffffu, vsel.y, 1);
                float m = vsel.x + vsel.y + vsel.z;
                float t = vsel.w + Rx;
                float4 sfv;
                sfv.x = Lz + Lw + m;
                sfv.y = Lw + m + vsel.w;
                sfv.z = m + t;
                sfv.w = vsel.y + vsel.z + t + Ry;
                // horizontal conv-output replication (cols 0,1 <- 2; 110,111 <- 109)
                if (tx == 0)       { sfv.x = sfv.z; sfv.y = sfv.z; }
                if (tx == NCG - 1) { sfv.z = sfv.y; sfv.w = sfv.y; }

                // numerator: raw xp of emitted row, straight from history
                const float4 xpv = hist[(i - 2) % 5];
                if (act && (i >= 6 || gband != 0)) {
                    const int hrow = r0 + i - 4;
                    float4 o;
                    o.x = fmaf(xpv.x, frcp(fmaf(sfv.x, k0w, spw)), bs);
                    o.y = fmaf(xpv.y, frcp(fmaf(sfv.y, k0w, spw)), bs);
                    o.z = fmaf(xpv.z, frcp(fmaf(sfv.z, k0w, spw)), bs);
                    o.w = fmaf(xpv.w, frcp(fmaf(sfv.w, k0w, spw)), bs);
                    *(float4*)&oimg[hrow * WW + w4] = o;
                }
                // rows 0,1 replicate sf(center 2) at i==6; reload x (L1 hit)
                if (i == 6) {
                    if (gband == 0 && act) {
                        #pragma unroll
                        for (int rr = 0; rr < 2; rr++) {
                            float4 vv = *(const float4*)&xin[rr * WW + w4];
                            float4 xq;
                            if (sq) { xq.x=vv.x*vv.x; xq.y=vv.y*vv.y; xq.z=vv.z*vv.z; xq.w=vv.w*vv.w; }
                            else    { xq.x=powf(vv.x,p); xq.y=powf(vv.y,p); xq.z=powf(vv.z,p); xq.w=powf(vv.w,p); }
                            float4 o;
                            o.x = fmaf(xq.x, frcp(fmaf(sfv.x, k0w, spw)), bs);
                            o.y = fmaf(xq.y, frcp(fmaf(sfv.y, k0w, spw)), bs);
                            o.z = fmaf(xq.z, frcp(fmaf(sfv.z, k0w, spw)), bs);
                            o.w = fmaf(xq.w, frcp(fmaf(sfv.w, k0w, spw)), bs);
                            *(float4*)&oimg[rr * WW + w4] = o;
                        }
                    }
                }
            }
        }
    } else {
        // ========== GENERAL PATH: direct 25-tap from global (fallback) =====
        if (act) {
            float kc[25];
            #pragma unroll
            for (int q = 0; q < 25; q++) kc[q] = kc_sh[q];
            for (int j = 0; j < BH; j++) {
                const int hrow = r0 + j;
                const int hc = iclamp(hrow, 2, HH - 3);
                float4 o;
                float* op = &o.x;
                #pragma unroll
                for (int jj = 0; jj < 4; jj++) {
                    const int w  = w4 + jj;
                    const int wc = iclamp(w, 2, WW - 3);
                    float acc = 0.0f;
                    #pragma unroll
                    for (int ki = 0; ki < 5; ki++) {
                        const float* row = &xin[(hc + ki - 2) * WW + (wc - 2)];
                        #pragma unroll
                        for (int kj = 0; kj < 5; kj++) {
                            float xv = row[kj];
                            float xpv = sq ? xv * xv : powf(xv, p);
                            acc = fmaf(kc[ki * 5 + kj], xpv, acc);
                        }
                    }
                    float xv = xin[hrow * WW + w];
                    float xpv = sq ? xv * xv : powf(xv, p);
                    op[jj] = wgt * xpv / (sp + acc) + bs;
                }
                *(float4*)&oimg[hrow * WW + w4] = o;
            }
        }
    }
}

extern "C" void kernel_launch(void* const* d_in, const int* in_sizes, int n_in,
                              void* d_out, int out_size)
{
    const float* x          = (const float*)d_in[0];
    const float* sigma      = (const float*)d_in[1];
    const float* pow_p      = (const float*)d_in[2];
    const float* sum_kernel = (const float*)d_in[3];
    const float* weight     = (const float*)d_in[4];
    const float* bias       = (const float*)d_in[5];
    float* out = (float*)d_out;

    dim3 grid(CCH, BBATCH, ZSPLIT);   // 4096 CTAs
    dim3 block(BX, BANDS, 1);         // 128 threads
    bionorm_kernel<<<grid, block>>>(x, sigma, pow_p, sum_kernel, weight, bias, out);
}